// round 15
// baseline (speedup 1.0000x reference)
#include <cuda_runtime.h>
#include <cuda_fp16.h>
#include <cstdint>

// ---------------------------------------------------------------------------
// Fused: h = x @ w^T + b ; instance-norm over OUT ; out = (norm(h)+y)*y
// Single fp16 m16n8k16 GEMM pass + Gram-identity row stats.
// R15 = R14 (167us) with:
//  (1) warp tile 32x32 -> 16x32 (MTILE 32, acc 16 regs) + launch_bounds(256,3)
//      -> 24 warps/SM (was 16), attacking the measured latency bind
//      (occ 21.7%, no pipe >56%).
//  (2) precompute: 3 launches -> 2, atomics-free partial-Gram + pack.
// ---------------------------------------------------------------------------

#define DEVINL __device__ __forceinline__

static constexpr int IN      = 128;
static constexpr int OUT     = 2048;
static constexpr int MTILE   = 32;
static constexpr int NCHUNK  = 128;
static constexpr int NCHUNKS = OUT / NCHUNK;   // 16
static constexpr int THREADS = 256;            // 8 warps: 2m x 4n (16x32 tiles)
static constexpr int SSTR    = 40;             // stage tile row stride (floats)
static constexpr int GBLK    = 16;             // gram rows per block
static constexpr int GNB     = OUT / GBLK;     // 128 gram blocks

// SMEM layout (floats)
static constexpr int X_OFF     = 0;                      // 4096 halves = 2048 f
static constexpr int STAGE_OFF = X_OFF + 2048;           // 8 warps x 16 x 40
static constexpr int MEAN_OFF  = STAGE_OFF + 8 * 16 * SSTR;
static constexpr int DOTC_OFF  = MEAN_OFF + MTILE;
static constexpr int SQ_OFF    = DOTC_OFF + MTILE;
static constexpr int ISTD_OFF  = SQ_OFF + MTILE;
static constexpr int TOTAL_F   = ISTD_OFF + MTILE;       // ~29.2 KB -> 3 CTAs/SM

// ---- device scratch ----
__device__ __align__(16) __half g_wh[OUT * IN];        // fragment-major fp16 w
__device__ __align__(16) __half g_Gh[IN * IN];         // Gram, fragment-major fp16
__device__ __align__(16) float  g_Gpart[GNB * IN * IN]; // partial Grams (8MB)
__device__ __align__(16) float  g_cpart[GNB * IN];
__device__ __align__(16) float  g_swpart[GNB * IN];
__device__ __align__(16) float  g_dbpart[GNB * 2];
__device__ __align__(16) float  g_c[IN];               // natural order
__device__ __align__(16) float  g_sw[IN];              // natural order
__device__ float g_db[2];

DEVINL float f16r(float f) {                           // fp16 round-trip (RNE)
    return __half2float(__float2half_rn(f));
}

DEVINL void mma_f16(float* c, uint32_t a0, uint32_t a1, uint32_t a2, uint32_t a3,
                    uint32_t b0, uint32_t b1) {
    asm volatile(
        "mma.sync.aligned.m16n8k16.row.col.f32.f16.f16.f32 "
        "{%0,%1,%2,%3}, {%4,%5,%6,%7}, {%8,%9}, {%0,%1,%2,%3};"
        : "+f"(c[0]), "+f"(c[1]), "+f"(c[2]), "+f"(c[3])
        : "r"(a0), "r"(a1), "r"(a2), "r"(a3), "r"(b0), "r"(b1));
}

// B-operand fragment-major half offset within a 128-row chunk (r, k in 0..127).
DEVINL int bh_off(int r, int k) {
    int rg = r >> 3, g = r & 7;
    int j = k >> 4, kin = k & 15;
    int hi = kin >> 3;
    int tg = (kin - hi * 8) >> 1;
    int pos = hi * 2 + (kin & 1);
    return rg * 1024 + (j >> 1) * 256 + (g * 4 + tg) * 8 + (j & 1) * 4 + pos;
}
// A-operand fragment-major half offset in x smem (r in 0..31, k in 0..127).
DEVINL int ah_off(int r, int k) {
    int rb = r >> 4, g = r & 7, h = (r >> 3) & 1;
    int j = k >> 4, kin = k & 15;
    int hi = kin >> 3;
    int tg = (kin - hi * 8) >> 1;
    int pos = h * 2 + hi * 4 + (kin & 1);
    return (rb * 8 + j) * 256 + (g * 4 + tg) * 8 + pos;
}

// ---------------- precompute (2 launches, atomics-free) ----------------

// Block t: rows [16t, 16t+16). Emits fp16 fragment-major w rows, a partial
// Gram (plain stores), partial c/sw/db.
__global__ __launch_bounds__(256, 1)
void gram_kernel(const float* __restrict__ w, const float* __restrict__ b) {
    __shared__ float ws[GBLK][IN];
    __shared__ float bs[GBLK];
    const int tid   = threadIdx.x;
    const int t     = blockIdx.x;
    const int jbase = t * GBLK;

    #pragma unroll
    for (int it = 0; it < 2; ++it) {
        int i  = it * 256 + tid;            // 512 float4 slots
        int j  = i >> 5;
        int c4 = (i & 31) * 4;
        float4 v = *reinterpret_cast<const float4*>(w + (size_t)(jbase + j) * IN + c4);
        ws[j][c4 + 0] = f16r(v.x);
        ws[j][c4 + 1] = f16r(v.y);
        ws[j][c4 + 2] = f16r(v.z);
        ws[j][c4 + 3] = f16r(v.w);
    }
    if (tid < GBLK) bs[tid] = b[jbase + tid];
    __syncthreads();

    // Emit fragment-major fp16 w.
    #pragma unroll
    for (int it = 0; it < 8; ++it) {
        int i = it * 256 + tid;             // 2048 elements
        int j = i >> 7;
        int k = i & 127;
        int R = jbase + j;
        g_wh[(size_t)(R >> 7) * (128 * IN) + bh_off(R & 127, k)] =
            __float2half_rn(ws[j][k]);
    }

    const int k     = tid & 127;
    const int lbase = (tid >> 7) * 64;
    float acc[64];
    #pragma unroll
    for (int l = 0; l < 64; ++l) acc[l] = 0.0f;
    float ck = 0.0f, swk = 0.0f;

    #pragma unroll
    for (int j = 0; j < GBLK; ++j) {
        float wk = ws[j][k];
        #pragma unroll
        for (int l = 0; l < 64; ++l) acc[l] += wk * ws[j][lbase + l];
        ck  += bs[j] * wk;
        swk += wk;
    }
    float* gp = g_Gpart + (size_t)t * (IN * IN) + k * IN + lbase;
    #pragma unroll
    for (int l4 = 0; l4 < 16; ++l4)
        *reinterpret_cast<float4*>(gp + l4 * 4) =
            make_float4(acc[l4 * 4], acc[l4 * 4 + 1], acc[l4 * 4 + 2], acc[l4 * 4 + 3]);
    if (tid < IN) {
        g_cpart[t * IN + k]  = ck;
        g_swpart[t * IN + k] = swk;
    }
    if (tid == 128) {
        float d0 = 0.0f, d1 = 0.0f;
        #pragma unroll
        for (int j = 0; j < GBLK; ++j) { d0 += bs[j] * bs[j]; d1 += bs[j]; }
        g_dbpart[t * 2 + 0] = d0;
        g_dbpart[t * 2 + 1] = d1;
    }
}

// Reduce 128 partials; emit fp16 fragment-major G and fp32 c/sw/db.
__global__ void pack_kernel() {
    int i = blockIdx.x * blockDim.x + threadIdx.x;   // 16384 threads
    float s = 0.0f;
    #pragma unroll 4
    for (int t = 0; t < GNB; ++t) s += g_Gpart[(size_t)t * (IN * IN) + i];
    int r = i >> 7, k = i & 127;
    g_Gh[bh_off(r, k)] = __float2half_rn(s);

    if (i < IN) {
        float cs = 0.0f, ss = 0.0f;
        #pragma unroll 4
        for (int t = 0; t < GNB; ++t) {
            cs += g_cpart[t * IN + i];
            ss += g_swpart[t * IN + i];
        }
        g_c[i]  = cs;
        g_sw[i] = ss;
    }
    if (i == 0) {
        float d0 = 0.0f, d1 = 0.0f;
        #pragma unroll 4
        for (int t = 0; t < GNB; ++t) { d0 += g_dbpart[t * 2]; d1 += g_dbpart[t * 2 + 1]; }
        g_db[0] = d0;
        g_db[1] = d1;
    }
}

// ---------------- main kernel ----------------

DEVINL void load_x_tile(__half* dst, const float* __restrict__ g, int tid) {
    #pragma unroll
    for (int it = 0; it < (MTILE * 32) / THREADS; ++it) {
        int i  = it * THREADS + tid;
        int r  = i >> 5;
        int c4 = (i & 31) * 4;
        float4 v = *reinterpret_cast<const float4*>(g + (size_t)r * IN + c4);
        float vv[4] = {v.x, v.y, v.z, v.w};
        #pragma unroll
        for (int e = 0; e < 4; ++e)
            dst[ah_off(r, c4 + e)] = __float2half_rn(vv[e]);
    }
}

// Warp-tile 16x32 GEMM, K=128, fp16 m16n8k16.
DEVINL void compute_chunk(const __half* __restrict__ xs, const __half* __restrict__ wg,
                          int rb0, int rg0, int lane, float acc[4][4]) {
    #pragma unroll
    for (int nt = 0; nt < 4; ++nt)
        #pragma unroll
        for (int q = 0; q < 4; ++q)
            acc[nt][q] = 0.0f;

    const int lane8 = lane * 8;

    uint4 bcur[4], bnxt[4];
    #pragma unroll
    for (int nt = 0; nt < 4; ++nt)
        bcur[nt] = *reinterpret_cast<const uint4*>(wg + (rg0 + nt) * 1024 + lane8);

    #pragma unroll
    for (int jp = 0; jp < 4; ++jp) {
        if (jp < 3) {
            #pragma unroll
            for (int nt = 0; nt < 4; ++nt)
                bnxt[nt] = *reinterpret_cast<const uint4*>(
                               wg + (rg0 + nt) * 1024 + (jp + 1) * 256 + lane8);
        }
        #pragma unroll
        for (int jo = 0; jo < 2; ++jo) {
            const int j = jp * 2 + jo;
            uint4 a = *reinterpret_cast<const uint4*>(
                          xs + (rb0 * 8 + j) * 256 + lane8);
            #pragma unroll
            for (int nt = 0; nt < 4; ++nt)
                mma_f16(acc[nt], a.x, a.y, a.z, a.w,
                        jo ? bcur[nt].z : bcur[nt].x,
                        jo ? bcur[nt].w : bcur[nt].y);
        }
        #pragma unroll
        for (int nt = 0; nt < 4; ++nt) bcur[nt] = bnxt[nt];
    }
}

__global__ __launch_bounds__(THREADS, 3)
void fused_lin_inorm_kernel(const float* __restrict__ x,
                            const float* __restrict__ y,
                            const float* __restrict__ lb,
                            const float* __restrict__ nw,
                            const float* __restrict__ nb,
                            float* __restrict__ out) {
    __shared__ float sm[TOTAL_F];
    const int tid  = threadIdx.x;
    const int wid  = tid >> 5;
    const int lane = tid & 31;
    const int g    = lane >> 2;
    const int tig  = lane & 3;
    const int m0   = (wid >> 2) * 16;     // 2 m-groups of 16 rows
    const int n0   = (wid & 3) * 32;      // 4 n-warps
    const int rb0  = wid >> 2;
    const int rg0  = n0 >> 3;
    const size_t row0 = (size_t)blockIdx.x * MTILE;

    __half* xs = reinterpret_cast<__half*>(sm + X_OFF);
    float*  st = sm + STAGE_OFF + wid * (16 * SSTR);   // warp-private stage

    if (tid < MTILE) sm[SQ_OFF + tid] = 0.0f;
    load_x_tile(xs, x + row0 * IN, tid);
    __syncthreads();

    // Per-row mean and x'.c from fp16-rounded global x (natural-order coeffs).
    if (tid < MTILE) {
        const float* xr = x + (row0 + tid) * IN;
        float dm = 0.0f, dc = 0.0f;
        #pragma unroll 8
        for (int k4 = 0; k4 < 32; ++k4) {
            float4 xv = __ldg(reinterpret_cast<const float4*>(xr + k4 * 4));
            float4 sv = __ldg(reinterpret_cast<const float4*>(g_sw + k4 * 4));
            float4 cv = __ldg(reinterpret_cast<const float4*>(g_c + k4 * 4));
            float x0 = f16r(xv.x), x1 = f16r(xv.y), x2 = f16r(xv.z), x3 = f16r(xv.w);
            dm += x0 * sv.x + x1 * sv.y + x2 * sv.z + x3 * sv.w;
            dc += x0 * cv.x + x1 * cv.y + x2 * cv.z + x3 * cv.w;
        }
        sm[MEAN_OFF + tid] = (dm + g_db[1]) * (1.0f / OUT);
        sm[DOTC_OFF + tid] = dc;
    }

    // ---- stats chunk: Z = x' @ Ghat ; rsq = sum Z .* x' per row ----
    {
        float acc[4][4];
        compute_chunk(xs, g_Gh, rb0, rg0, lane, acc);

        float rsq[2] = {0.f, 0.f};
        #pragma unroll
        for (int h = 0; h < 2; ++h) {
            const int r = m0 + h * 8 + g;
            #pragma unroll
            for (int nt = 0; nt < 4; ++nt)
                #pragma unroll
                for (int p = 0; p < 2; ++p) {
                    int col = n0 + nt * 8 + tig * 2 + p;
                    rsq[h] += acc[nt][h * 2 + p] * __half2float(xs[ah_off(r, col)]);
                }
        }
        #pragma unroll
        for (int j = 0; j < 2; ++j) {
            rsq[j] += __shfl_xor_sync(0xffffffffu, rsq[j], 1);
            rsq[j] += __shfl_xor_sync(0xffffffffu, rsq[j], 2);
        }
        if (tig == 0) {
            atomicAdd(&sm[SQ_OFF + m0 + g], rsq[0]);
            atomicAdd(&sm[SQ_OFF + m0 + 8 + g], rsq[1]);
        }
    }
    __syncthreads();

    if (tid < MTILE) {
        float sumsq = sm[SQ_OFF + tid] + 2.0f * sm[DOTC_OFF + tid] + g_db[0];
        float mean  = sm[MEAN_OFF + tid];
        float var   = sumsq * (1.0f / OUT) - mean * mean;
        sm[ISTD_OFF + tid] = rsqrtf(var + 1e-5f);
    }
    __syncthreads();

    // Per-lane epilogue row constants (iteration j covers rows j*4 + (lane>>3)).
    const int rl = lane >> 3;       // 0..3
    const int cl = (lane & 7) * 4;  // 0,4,...,28
    float meanv[4], istdv[4];
    #pragma unroll
    for (int j = 0; j < 4; ++j) {
        int r = m0 + j * 4 + rl;
        meanv[j] = sm[MEAN_OFF + r];
        istdv[j] = sm[ISTD_OFF + r];
    }

    // ---------------- main loop: 16 chunks, NO CTA barriers ----------------
    #pragma unroll 1
    for (int ch = 0; ch < NCHUNKS; ++ch) {
        float acc[4][4];
        compute_chunk(xs, g_wh + (size_t)ch * NCHUNK * IN, rb0, rg0, lane, acc);

        // Stage the 16x32 acc tile into warp-private smem (conflict-free).
        #pragma unroll
        for (int h = 0; h < 2; ++h)
            #pragma unroll
            for (int nt = 0; nt < 4; ++nt) {
                float2 v = make_float2(acc[nt][h * 2 + 0], acc[nt][h * 2 + 1]);
                *reinterpret_cast<float2*>(
                    st + (h * 8 + g) * SSTR + nt * 8 + tig * 2) = v;
            }
        __syncwarp();

        // Coalesced readback + fused epilogue (float4, 4 lines/instr).
        const int cbase = ch * NCHUNK + n0;
        float4 lbv = __ldg(reinterpret_cast<const float4*>(lb + cbase + cl));
        float4 nwv = __ldg(reinterpret_cast<const float4*>(nw + cbase + cl));
        float4 nbv = __ldg(reinterpret_cast<const float4*>(nb + cbase + cl));

        #pragma unroll
        for (int j = 0; j < 4; ++j) {
            const int r = j * 4 + rl;            // local row 0..15
            float4 v = *reinterpret_cast<const float4*>(st + r * SSTR + cl);
            const size_t grow = row0 + (size_t)(m0 + r);
            float4 yv = __ldg(reinterpret_cast<const float4*>(y + grow * OUT + cbase + cl));
            const float mean = meanv[j], istd = istdv[j];
            float4 ov;
            float nm;
            nm = ((v.x + lbv.x) - mean) * istd * nwv.x + nbv.x; ov.x = (nm + yv.x) * yv.x;
            nm = ((v.y + lbv.y) - mean) * istd * nwv.y + nbv.y; ov.y = (nm + yv.y) * yv.y;
            nm = ((v.z + lbv.z) - mean) * istd * nwv.z + nbv.z; ov.z = (nm + yv.z) * yv.z;
            nm = ((v.w + lbv.w) - mean) * istd * nwv.w + nbv.w; ov.w = (nm + yv.w) * yv.w;
            *reinterpret_cast<float4*>(out + grow * OUT + cbase + cl) = ov;
        }
        __syncwarp();   // stage buffer reusable next chunk
    }
}

extern "C" void kernel_launch(void* const* d_in, const int* in_sizes, int n_in,
                              void* d_out, int out_size) {
    (void)n_in; (void)out_size;
    const float* x  = (const float*)d_in[0];
    const float* y  = (const float*)d_in[1];
    const float* w  = (const float*)d_in[2];
    const float* lb = (const float*)d_in[3];
    const float* nw = (const float*)d_in[4];
    const float* nb = (const float*)d_in[5];
    float* out = (float*)d_out;

    const int rows = in_sizes[0] / IN;   // 32768
    const int grid = rows / MTILE;       // 1024

    gram_kernel<<<GNB, 256>>>(w, lb);
    pack_kernel<<<IN * IN / 256, 256>>>();
    fused_lin_inorm_kernel<<<grid, THREADS>>>(x, y, lb, nw, nb, out);
}

// round 16
// speedup vs baseline: 1.1760x; 1.1760x over previous
#include <cuda_runtime.h>
#include <cuda_fp16.h>
#include <cstdint>

// ---------------------------------------------------------------------------
// Fused: h = x @ w^T + b ; instance-norm over OUT ; out = (norm(h)+y)*y
// Single fp16 m16n8k16 GEMM pass + Gram-identity row stats.
// R16 = R14 main kernel (measured 139.7us: MTILE=64, 32x32 warp tiles,
// 2 CTAs/SM, fragment-major operands, coalesced staged epilogue) +
// R15's 2-launch atomics-free precompute (measured ~12us vs 27.6us).
// R15's MTILE=32 reverted: it doubled total w traffic (grid-proportional).
// ---------------------------------------------------------------------------

#define DEVINL __device__ __forceinline__

static constexpr int IN      = 128;
static constexpr int OUT     = 2048;
static constexpr int MTILE   = 64;
static constexpr int NCHUNK  = 128;
static constexpr int NCHUNKS = OUT / NCHUNK;   // 16
static constexpr int THREADS = 256;            // 8 warps: 2m x 4n (32x32 tiles)
static constexpr int SSTR    = 40;             // stage tile row stride (floats)
static constexpr int GBLK    = 16;             // gram rows per block
static constexpr int GNB     = OUT / GBLK;     // 128 gram blocks

// SMEM layout (floats)
static constexpr int X_OFF     = 0;                      // 8192 halves = 4096 f
static constexpr int STAGE_OFF = X_OFF + 4096;           // 8 warps x 32 x 40
static constexpr int MEAN_OFF  = STAGE_OFF + 8 * 32 * SSTR;
static constexpr int DOTC_OFF  = MEAN_OFF + MTILE;
static constexpr int SQ_OFF    = DOTC_OFF + MTILE;
static constexpr int ISTD_OFF  = SQ_OFF + MTILE;
static constexpr int TOTAL_F   = ISTD_OFF + MTILE;       // ~58.4 KB

// ---- device scratch ----
__device__ __align__(16) __half g_wh[OUT * IN];         // fragment-major fp16 w
__device__ __align__(16) __half g_Gh[IN * IN];          // Gram, fragment-major fp16
__device__ __align__(16) float  g_Gpart[GNB * IN * IN]; // partial Grams (8MB)
__device__ __align__(16) float  g_cpart[GNB * IN];
__device__ __align__(16) float  g_swpart[GNB * IN];
__device__ __align__(16) float  g_dbpart[GNB * 2];
__device__ __align__(16) float  g_c[IN];                // natural order
__device__ __align__(16) float  g_sw[IN];               // natural order
__device__ float g_db[2];

DEVINL float f16r(float f) {                            // fp16 round-trip (RNE)
    return __half2float(__float2half_rn(f));
}

DEVINL void mma_f16(float* c, uint32_t a0, uint32_t a1, uint32_t a2, uint32_t a3,
                    uint32_t b0, uint32_t b1) {
    asm volatile(
        "mma.sync.aligned.m16n8k16.row.col.f32.f16.f16.f32 "
        "{%0,%1,%2,%3}, {%4,%5,%6,%7}, {%8,%9}, {%0,%1,%2,%3};"
        : "+f"(c[0]), "+f"(c[1]), "+f"(c[2]), "+f"(c[3])
        : "r"(a0), "r"(a1), "r"(a2), "r"(a3), "r"(b0), "r"(b1));
}

// B-operand fragment-major half offset within a 128-row chunk (r, k in 0..127).
DEVINL int bh_off(int r, int k) {
    int rg = r >> 3, g = r & 7;
    int j = k >> 4, kin = k & 15;
    int hi = kin >> 3;
    int tg = (kin - hi * 8) >> 1;
    int pos = hi * 2 + (kin & 1);
    return rg * 1024 + (j >> 1) * 256 + (g * 4 + tg) * 8 + (j & 1) * 4 + pos;
}
// A-operand fragment-major half offset in x smem (r in 0..63, k in 0..127).
DEVINL int ah_off(int r, int k) {
    int rb = r >> 4, g = r & 7, h = (r >> 3) & 1;
    int j = k >> 4, kin = k & 15;
    int hi = kin >> 3;
    int tg = (kin - hi * 8) >> 1;
    int pos = h * 2 + hi * 4 + (kin & 1);
    return (rb * 8 + j) * 256 + (g * 4 + tg) * 8 + pos;
}

// ---------------- precompute (2 launches, atomics-free) ----------------

// Block t: rows [16t, 16t+16). Emits fp16 fragment-major w rows, a partial
// Gram (plain stores), partial c/sw/db.
__global__ __launch_bounds__(256, 1)
void gram_kernel(const float* __restrict__ w, const float* __restrict__ b) {
    __shared__ float ws[GBLK][IN];
    __shared__ float bs[GBLK];
    const int tid   = threadIdx.x;
    const int t     = blockIdx.x;
    const int jbase = t * GBLK;

    #pragma unroll
    for (int it = 0; it < 2; ++it) {
        int i  = it * 256 + tid;            // 512 float4 slots
        int j  = i >> 5;
        int c4 = (i & 31) * 4;
        float4 v = *reinterpret_cast<const float4*>(w + (size_t)(jbase + j) * IN + c4);
        ws[j][c4 + 0] = f16r(v.x);
        ws[j][c4 + 1] = f16r(v.y);
        ws[j][c4 + 2] = f16r(v.z);
        ws[j][c4 + 3] = f16r(v.w);
    }
    if (tid < GBLK) bs[tid] = b[jbase + tid];
    __syncthreads();

    // Emit fragment-major fp16 w.
    #pragma unroll
    for (int it = 0; it < 8; ++it) {
        int i = it * 256 + tid;             // 2048 elements
        int j = i >> 7;
        int k = i & 127;
        int R = jbase + j;
        g_wh[(size_t)(R >> 7) * (128 * IN) + bh_off(R & 127, k)] =
            __float2half_rn(ws[j][k]);
    }

    const int k     = tid & 127;
    const int lbase = (tid >> 7) * 64;
    float acc[64];
    #pragma unroll
    for (int l = 0; l < 64; ++l) acc[l] = 0.0f;
    float ck = 0.0f, swk = 0.0f;

    #pragma unroll
    for (int j = 0; j < GBLK; ++j) {
        float wk = ws[j][k];
        #pragma unroll
        for (int l = 0; l < 64; ++l) acc[l] += wk * ws[j][lbase + l];
        ck  += bs[j] * wk;
        swk += wk;
    }
    float* gp = g_Gpart + (size_t)t * (IN * IN) + k * IN + lbase;
    #pragma unroll
    for (int l4 = 0; l4 < 16; ++l4)
        *reinterpret_cast<float4*>(gp + l4 * 4) =
            make_float4(acc[l4 * 4], acc[l4 * 4 + 1], acc[l4 * 4 + 2], acc[l4 * 4 + 3]);
    if (tid < IN) {
        g_cpart[t * IN + k]  = ck;
        g_swpart[t * IN + k] = swk;
    }
    if (tid == 128) {
        float d0 = 0.0f, d1 = 0.0f;
        #pragma unroll
        for (int j = 0; j < GBLK; ++j) { d0 += bs[j] * bs[j]; d1 += bs[j]; }
        g_dbpart[t * 2 + 0] = d0;
        g_dbpart[t * 2 + 1] = d1;
    }
}

// Reduce 128 partials; emit fp16 fragment-major G and fp32 c/sw/db.
__global__ void pack_kernel() {
    int i = blockIdx.x * blockDim.x + threadIdx.x;   // 16384 threads
    float s = 0.0f;
    #pragma unroll 4
    for (int t = 0; t < GNB; ++t) s += g_Gpart[(size_t)t * (IN * IN) + i];
    int r = i >> 7, k = i & 127;
    g_Gh[bh_off(r, k)] = __float2half_rn(s);

    if (i < IN) {
        float cs = 0.0f, ss = 0.0f;
        #pragma unroll 4
        for (int t = 0; t < GNB; ++t) {
            cs += g_cpart[t * IN + i];
            ss += g_swpart[t * IN + i];
        }
        g_c[i]  = cs;
        g_sw[i] = ss;
    }
    if (i == 0) {
        float d0 = 0.0f, d1 = 0.0f;
        #pragma unroll 4
        for (int t = 0; t < GNB; ++t) { d0 += g_dbpart[t * 2]; d1 += g_dbpart[t * 2 + 1]; }
        g_db[0] = d0;
        g_db[1] = d1;
    }
}

// ---------------- main kernel (R14 verbatim) ----------------

DEVINL void load_x_tile(__half* dst, const float* __restrict__ g, int tid) {
    #pragma unroll
    for (int it = 0; it < (MTILE * 32) / THREADS; ++it) {
        int i  = it * THREADS + tid;
        int r  = i >> 5;
        int c4 = (i & 31) * 4;
        float4 v = *reinterpret_cast<const float4*>(g + (size_t)r * IN + c4);
        float vv[4] = {v.x, v.y, v.z, v.w};
        #pragma unroll
        for (int e = 0; e < 4; ++e)
            dst[ah_off(r, c4 + e)] = __float2half_rn(vv[e]);
    }
}

// Warp-tile 32x32 GEMM, K=128, fp16 m16n8k16.
DEVINL void compute_chunk(const __half* __restrict__ xs, const __half* __restrict__ wg,
                          int rb0, int rg0, int lane, float acc[2][4][4]) {
    #pragma unroll
    for (int mt = 0; mt < 2; ++mt)
        #pragma unroll
        for (int nt = 0; nt < 4; ++nt)
            #pragma unroll
            for (int q = 0; q < 4; ++q)
                acc[mt][nt][q] = 0.0f;

    const int lane8 = lane * 8;

    uint4 bcur[4], bnxt[4];
    #pragma unroll
    for (int nt = 0; nt < 4; ++nt)
        bcur[nt] = *reinterpret_cast<const uint4*>(wg + (rg0 + nt) * 1024 + lane8);

    #pragma unroll
    for (int jp = 0; jp < 4; ++jp) {
        if (jp < 3) {
            #pragma unroll
            for (int nt = 0; nt < 4; ++nt)
                bnxt[nt] = *reinterpret_cast<const uint4*>(
                               wg + (rg0 + nt) * 1024 + (jp + 1) * 256 + lane8);
        }
        #pragma unroll
        for (int jo = 0; jo < 2; ++jo) {
            const int j = jp * 2 + jo;
            uint4 a[2];
            #pragma unroll
            for (int mt = 0; mt < 2; ++mt)
                a[mt] = *reinterpret_cast<const uint4*>(
                            xs + ((rb0 + mt) * 8 + j) * 256 + lane8);
            #pragma unroll
            for (int mt = 0; mt < 2; ++mt)
                #pragma unroll
                for (int nt = 0; nt < 4; ++nt)
                    mma_f16(acc[mt][nt], a[mt].x, a[mt].y, a[mt].z, a[mt].w,
                            jo ? bcur[nt].z : bcur[nt].x,
                            jo ? bcur[nt].w : bcur[nt].y);
        }
        #pragma unroll
        for (int nt = 0; nt < 4; ++nt) bcur[nt] = bnxt[nt];
    }
}

__global__ __launch_bounds__(THREADS, 2)
void fused_lin_inorm_kernel(const float* __restrict__ x,
                            const float* __restrict__ y,
                            const float* __restrict__ lb,
                            const float* __restrict__ nw,
                            const float* __restrict__ nb,
                            float* __restrict__ out) {
    __shared__ float sm[TOTAL_F];
    const int tid  = threadIdx.x;
    const int wid  = tid >> 5;
    const int lane = tid & 31;
    const int g    = lane >> 2;
    const int tig  = lane & 3;
    const int m0   = (wid >> 2) * 32;
    const int n0   = (wid & 3) * 32;
    const int rb0  = m0 >> 4;
    const int rg0  = n0 >> 3;
    const size_t row0 = (size_t)blockIdx.x * MTILE;

    __half* xs = reinterpret_cast<__half*>(sm + X_OFF);
    float*  st = sm + STAGE_OFF + wid * (32 * SSTR);   // warp-private stage

    if (tid < MTILE) sm[SQ_OFF + tid] = 0.0f;
    load_x_tile(xs, x + row0 * IN, tid);
    __syncthreads();

    // Per-row mean and x'.c from fp16-rounded global x (natural-order coeffs).
    if (tid < MTILE) {
        const float* xr = x + (row0 + tid) * IN;
        float dm = 0.0f, dc = 0.0f;
        #pragma unroll 8
        for (int k4 = 0; k4 < 32; ++k4) {
            float4 xv = __ldg(reinterpret_cast<const float4*>(xr + k4 * 4));
            float4 sv = __ldg(reinterpret_cast<const float4*>(g_sw + k4 * 4));
            float4 cv = __ldg(reinterpret_cast<const float4*>(g_c + k4 * 4));
            float x0 = f16r(xv.x), x1 = f16r(xv.y), x2 = f16r(xv.z), x3 = f16r(xv.w);
            dm += x0 * sv.x + x1 * sv.y + x2 * sv.z + x3 * sv.w;
            dc += x0 * cv.x + x1 * cv.y + x2 * cv.z + x3 * cv.w;
        }
        sm[MEAN_OFF + tid] = (dm + g_db[1]) * (1.0f / OUT);
        sm[DOTC_OFF + tid] = dc;
    }

    // ---- stats chunk: Z = x' @ Ghat ; rsq = sum Z .* x' per row ----
    {
        float acc[2][4][4];
        compute_chunk(xs, g_Gh, rb0, rg0, lane, acc);

        float rsq[4] = {0.f, 0.f, 0.f, 0.f};
        #pragma unroll
        for (int mt = 0; mt < 2; ++mt)
            #pragma unroll
            for (int h = 0; h < 2; ++h) {
                const int r = m0 + mt * 16 + h * 8 + g;
                #pragma unroll
                for (int nt = 0; nt < 4; ++nt)
                    #pragma unroll
                    for (int p = 0; p < 2; ++p) {
                        int col = n0 + nt * 8 + tig * 2 + p;
                        rsq[mt * 2 + h] += acc[mt][nt][h * 2 + p] *
                                           __half2float(xs[ah_off(r, col)]);
                    }
            }
        #pragma unroll
        for (int j = 0; j < 4; ++j) {
            rsq[j] += __shfl_xor_sync(0xffffffffu, rsq[j], 1);
            rsq[j] += __shfl_xor_sync(0xffffffffu, rsq[j], 2);
        }
        if (tig == 0) {
            #pragma unroll
            for (int j = 0; j < 4; ++j) {
                int r = m0 + (j >> 1) * 16 + (j & 1) * 8 + g;
                atomicAdd(&sm[SQ_OFF + r], rsq[j]);
            }
        }
    }
    __syncthreads();

    if (tid < MTILE) {
        float sumsq = sm[SQ_OFF + tid] + 2.0f * sm[DOTC_OFF + tid] + g_db[0];
        float mean  = sm[MEAN_OFF + tid];
        float var   = sumsq * (1.0f / OUT) - mean * mean;
        sm[ISTD_OFF + tid] = rsqrtf(var + 1e-5f);
    }
    __syncthreads();

    // Per-lane epilogue row constants (iteration j covers rows j*4 + (lane>>3)).
    const int rl = lane >> 3;       // 0..3
    const int cl = (lane & 7) * 4;  // 0,4,...,28
    float meanv[8], istdv[8];
    #pragma unroll
    for (int j = 0; j < 8; ++j) {
        int r = m0 + j * 4 + rl;
        meanv[j] = sm[MEAN_OFF + r];
        istdv[j] = sm[ISTD_OFF + r];
    }

    // ---------------- main loop: 16 chunks, NO CTA barriers ----------------
    #pragma unroll 1
    for (int ch = 0; ch < NCHUNKS; ++ch) {
        float acc[2][4][4];
        compute_chunk(xs, g_wh + (size_t)ch * NCHUNK * IN, rb0, rg0, lane, acc);

        // Stage the 32x32 acc tile into warp-private smem (conflict-free).
        #pragma unroll
        for (int mt = 0; mt < 2; ++mt)
            #pragma unroll
            for (int h = 0; h < 2; ++h)
                #pragma unroll
                for (int nt = 0; nt < 4; ++nt) {
                    float2 v = make_float2(acc[mt][nt][h * 2 + 0], acc[mt][nt][h * 2 + 1]);
                    *reinterpret_cast<float2*>(
                        st + (mt * 16 + h * 8 + g) * SSTR + nt * 8 + tig * 2) = v;
                }
        __syncwarp();

        // Coalesced readback + fused epilogue (float4, 4 lines/instr).
        const int cbase = ch * NCHUNK + n0;
        float4 lbv = __ldg(reinterpret_cast<const float4*>(lb + cbase + cl));
        float4 nwv = __ldg(reinterpret_cast<const float4*>(nw + cbase + cl));
        float4 nbv = __ldg(reinterpret_cast<const float4*>(nb + cbase + cl));

        #pragma unroll
        for (int j = 0; j < 8; ++j) {
            const int r = j * 4 + rl;
            float4 v = *reinterpret_cast<const float4*>(st + r * SSTR + cl);
            const size_t grow = row0 + (size_t)(m0 + r);
            float4 yv = __ldg(reinterpret_cast<const float4*>(y + grow * OUT + cbase + cl));
            const float mean = meanv[j], istd = istdv[j];
            float4 ov;
            float nm;
            nm = ((v.x + lbv.x) - mean) * istd * nwv.x + nbv.x; ov.x = (nm + yv.x) * yv.x;
            nm = ((v.y + lbv.y) - mean) * istd * nwv.y + nbv.y; ov.y = (nm + yv.y) * yv.y;
            nm = ((v.z + lbv.z) - mean) * istd * nwv.z + nbv.z; ov.z = (nm + yv.z) * yv.z;
            nm = ((v.w + lbv.w) - mean) * istd * nwv.w + nbv.w; ov.w = (nm + yv.w) * yv.w;
            *reinterpret_cast<float4*>(out + grow * OUT + cbase + cl) = ov;
        }
        __syncwarp();   // stage buffer reusable next chunk
    }
}

extern "C" void kernel_launch(void* const* d_in, const int* in_sizes, int n_in,
                              void* d_out, int out_size) {
    (void)n_in; (void)out_size;
    const float* x  = (const float*)d_in[0];
    const float* y  = (const float*)d_in[1];
    const float* w  = (const float*)d_in[2];
    const float* lb = (const float*)d_in[3];
    const float* nw = (const float*)d_in[4];
    const float* nb = (const float*)d_in[5];
    float* out = (float*)d_out;

    const int rows = in_sizes[0] / IN;   // 32768
    const int grid = rows / MTILE;       // 512

    gram_kernel<<<GNB, 256>>>(w, lb);
    pack_kernel<<<IN * IN / 256, 256>>>();
    fused_lin_inorm_kernel<<<grid, THREADS>>>(x, y, lb, nw, nb, out);
}